// round 16
// baseline (speedup 1.0000x reference)
#include <cuda_runtime.h>
#include <cstdint>
#include <math.h>

#define EPS_BN 1e-5f

// ---- problem constants ----
#define B_EP   32
#define NS     200
#define NQ     100
#define NWAY   20
#define CIN    8
#define LIN    512
#define FDIM   128
#define NSUP   (B_EP*NS)     // 6400
#define NQRY   (B_EP*NQ)     // 3200
#define NTOT   (NSUP+NQRY)   // 9600
#define NT     256           // encoder threads per CTA (2 CTAs/SM)

typedef unsigned long long ull;

// ---- device scratch ----
__device__ float g_feat[NTOT*FDIM];
__device__ float g_proto[B_EP*NWAY*FDIM];
// pre-interleaved weights + folded BN (written once by prep_kernel)
__device__ float g_w1p[768];        // [pair][ic*3][2]
__device__ float g_w2p[6144];       // [pair][ic*3][2]
__device__ float g_w3p[24576];      // [pair][ic*3][2]  (pair stride 384 floats)
__device__ float g_sc1[32],  g_bi1[32];
__device__ float g_sc2[64],  g_bi2[64];
__device__ float g_sc3[128], g_bi3[128];   // include 1/64 mean fold
__device__ float g_scf[128], g_bif[128];

// ---- shared memory layout (float offsets), total 19520 floats = 78.1KB ----
#define OFF_S1   0            // 32 x 260 = 8320 (stable now — no aliasing)
#define OFF_S2   8320         // 64 x 132 = 8448
#define OFF_W2   16768        // 6144
#define OFF_W1   22912        // wait — keep order tight below
// recompute: S1 8320, S2 8448 -> 16768, W2 6144 -> 22912, W1 768 -> 23680,
// F3 128 -> 23808, RED 32 -> 23840
#undef OFF_W1
#define OFF_W1   22912
#define OFF_F3   23680
#define OFF_RED  23808
#define SMEM_FLOATS 23840
#define SMEM_BYTES  (SMEM_FLOATS*4)

// ---- packed f32x2 helpers ----
__device__ __forceinline__ ull ffma2(ull a, ull b, ull c) {
    ull d;
    asm("fma.rn.f32x2 %0, %1, %2, %3;" : "=l"(d) : "l"(a), "l"(b), "l"(c));
    return d;
}
__device__ __forceinline__ ull splat2(float x) {
    ull d;
    asm("mov.b64 %0, {%1, %1};" : "=l"(d) : "f"(x));
    return d;
}
__device__ __forceinline__ void unpack2(ull v, float& lo, float& hi) {
    asm("mov.b64 {%0, %1}, %2;" : "=f"(lo), "=f"(hi) : "l"(v));
}
__device__ __forceinline__ uint32_t smem_u32(const void* p) {
    uint32_t a;
    asm("{ .reg .u64 t; cvta.to.shared.u64 t, %1; cvt.u32.u64 %0, t; }"
        : "=r"(a) : "l"(p));
    return a;
}
__device__ __forceinline__ void cp_async16(uint32_t saddr, const void* g) {
    asm volatile("cp.async.cg.shared.global [%0], [%1], 16;" :: "r"(saddr), "l"(g));
}
__device__ __forceinline__ void cp_async_commit() {
    asm volatile("cp.async.commit_group;" ::: "memory");
}
template<int N>
__device__ __forceinline__ void cp_async_wait() {
    asm volatile("cp.async.wait_group %0;" :: "n"(N) : "memory");
}

// ---- one-time prep (grid=24): pair-interleave conv weights, fold BN ----
__global__ __launch_bounds__(512)
void prep_kernel(const float* __restrict__ w1, const float* __restrict__ b1,
                 const float* __restrict__ g1, const float* __restrict__ be1,
                 const float* __restrict__ m1, const float* __restrict__ v1,
                 const float* __restrict__ w2, const float* __restrict__ b2,
                 const float* __restrict__ g2, const float* __restrict__ be2,
                 const float* __restrict__ m2, const float* __restrict__ v2,
                 const float* __restrict__ w3, const float* __restrict__ b3,
                 const float* __restrict__ g3, const float* __restrict__ be3,
                 const float* __restrict__ m3, const float* __restrict__ v3,
                 const float* __restrict__ bf, const float* __restrict__ gf,
                 const float* __restrict__ bef, const float* __restrict__ mf,
                 const float* __restrict__ vf)
{
    const int t = blockIdx.x*512 + threadIdx.x;
    const int STR = gridDim.x*512;
    for (int f = t; f < 768; f += STR) {
        int o = f/24, r = f - o*24;
        g_w1p[(o>>1)*48 + 2*r + (o&1)] = w1[f];
    }
    for (int f = t; f < 6144; f += STR) {
        int o = f/96, r = f - o*96;
        g_w2p[(o>>1)*192 + 2*r + (o&1)] = w2[f];
    }
    // full pair-interleave: w3[o][i][k] -> g_w3p[(o>>1)*384 + 2*r + (o&1)]
    for (int f = t; f < 24576; f += STR) {
        int o = f/192, r = f - o*192;
        g_w3p[(o>>1)*384 + 2*r + (o&1)] = w3[f];
    }
    if (t < 32) {
        float s = g1[t]*rsqrtf(v1[t]+EPS_BN);
        g_sc1[t]=s; g_bi1[t]=(b1[t]-m1[t])*s+be1[t];
    } else if (t < 96) {
        int i=t-32; float s = g2[i]*rsqrtf(v2[i]+EPS_BN);
        g_sc2[i]=s; g_bi2[i]=(b2[i]-m2[i])*s+be2[i];
    } else if (t < 224) {
        // fold 1/64 AdaptiveAvgPool mean into BN scale/bias
        int i=t-96; float s = g3[i]*rsqrtf(v3[i]+EPS_BN);
        g_sc3[i]=s*(1.0f/64.0f);
        g_bi3[i]=((b3[i]-m3[i])*s+be3[i])*(1.0f/64.0f);
    } else if (t < 352) {
        int i=t-224; float s = gf[i]*rsqrtf(vf[i]+EPS_BN);
        g_scf[i]=s; g_bif[i]=(bf[i]-mf[i])*s+bef[i];
    }
}

// Accumulate conv1d(k=3) into packed acc[2 pairs][8 positions], x and W in smem.
template<int IC, int XRS>
__device__ __forceinline__ void conv_accum(const float* __restrict__ xcol,
                                           const ull* __restrict__ wbase,
                                           ull (&acc)[2][8])
{
    constexpr int IC3 = IC*3;
    #pragma unroll 4
    for (int i = 0; i < IC; ++i) {
        const float* xr = xcol + i*XRS;
        float4 xa = *reinterpret_cast<const float4*>(xr);
        float4 xb = *reinterpret_cast<const float4*>(xr + 4);
        float2 xc = *reinterpret_cast<const float2*>(xr + 8);
        ull xs[10];
        xs[0]=splat2(xa.x); xs[1]=splat2(xa.y); xs[2]=splat2(xa.z); xs[3]=splat2(xa.w);
        xs[4]=splat2(xb.x); xs[5]=splat2(xb.y); xs[6]=splat2(xb.z); xs[7]=splat2(xb.w);
        xs[8]=splat2(xc.x); xs[9]=splat2(xc.y);
        const ull* w0r = wbase + 3*i;
        const ull* w1r = wbase + IC3 + 3*i;
        ull wa0 = w0r[0], wa1 = w0r[1], wa2 = w0r[2];
        ull wb0 = w1r[0], wb1 = w1r[1], wb2 = w1r[2];
        #pragma unroll
        for (int j = 0; j < 8; ++j) {
            acc[0][j] = ffma2(wa2, xs[j+2], ffma2(wa1, xs[j+1], ffma2(wa0, xs[j], acc[0][j])));
            acc[1][j] = ffma2(wb2, xs[j+2], ffma2(wb1, xs[j+1], ffma2(wb0, xs[j], acc[1][j])));
        }
    }
}

// Same but weights via uniform __ldg from global (L1/L2-resident; warp-uniform).
template<int IC, int XRS>
__device__ __forceinline__ void conv_accum_g(const float* __restrict__ xcol,
                                             const ull* __restrict__ wp,
                                             ull (&acc)[2][8])
{
    constexpr int IC3 = IC*3;
    #pragma unroll 4
    for (int i = 0; i < IC; ++i) {
        const float* xr = xcol + i*XRS;
        float4 xa = *reinterpret_cast<const float4*>(xr);
        float4 xb = *reinterpret_cast<const float4*>(xr + 4);
        float2 xc = *reinterpret_cast<const float2*>(xr + 8);
        ull xs[10];
        xs[0]=splat2(xa.x); xs[1]=splat2(xa.y); xs[2]=splat2(xa.z); xs[3]=splat2(xa.w);
        xs[4]=splat2(xb.x); xs[5]=splat2(xb.y); xs[6]=splat2(xb.z); xs[7]=splat2(xb.w);
        xs[8]=splat2(xc.x); xs[9]=splat2(xc.y);
        ull wa0 = __ldg(wp + 3*i),     wa1 = __ldg(wp + 3*i + 1),     wa2 = __ldg(wp + 3*i + 2);
        ull wb0 = __ldg(wp + IC3+3*i), wb1 = __ldg(wp + IC3+3*i + 1), wb2 = __ldg(wp + IC3+3*i + 2);
        #pragma unroll
        for (int j = 0; j < 8; ++j) {
            acc[0][j] = ffma2(wa2, xs[j+2], ffma2(wa1, xs[j+1], ffma2(wa0, xs[j], acc[0][j])));
            acc[1][j] = ffma2(wb2, xs[j+2], ffma2(wb1, xs[j+1], ffma2(wb0, xs[j], acc[1][j])));
        }
    }
}

// Epilogue: packed BN + ReLU + maxpool2, store 4 pooled per channel.
__device__ __forceinline__ void conv_epi_store(ull (&acc)[2][8], int o0, int q,
                                               const ull* __restrict__ scp,
                                               const ull* __restrict__ bip,
                                               float* __restrict__ Y, int YRS)
{
    #pragma unroll
    for (int p = 0; p < 2; ++p) {
        int pr = (o0 >> 1) + p;
        ull s2 = __ldg(scp + pr), b2 = __ldg(bip + pr);
        float a[8], b[8];
        #pragma unroll
        for (int j = 0; j < 8; ++j) {
            ull y = ffma2(acc[p][j], s2, b2);
            unpack2(y, a[j], b[j]);
        }
        float pA0 = fmaxf(fmaxf(a[0],0.f), fmaxf(a[1],0.f));
        float pA1 = fmaxf(fmaxf(a[2],0.f), fmaxf(a[3],0.f));
        float pA2 = fmaxf(fmaxf(a[4],0.f), fmaxf(a[5],0.f));
        float pA3 = fmaxf(fmaxf(a[6],0.f), fmaxf(a[7],0.f));
        float pB0 = fmaxf(fmaxf(b[0],0.f), fmaxf(b[1],0.f));
        float pB1 = fmaxf(fmaxf(b[2],0.f), fmaxf(b[3],0.f));
        float pB2 = fmaxf(fmaxf(b[4],0.f), fmaxf(b[5],0.f));
        float pB3 = fmaxf(fmaxf(b[6],0.f), fmaxf(b[7],0.f));
        float* yrA = Y + (2*pr)*YRS + 1 + 4*q;
        float* yrB = Y + (2*pr+1)*YRS + 1 + 4*q;
        yrA[0]=pA0; yrA[1]=pA1; yrA[2]=pA2; yrA[3]=pA3;
        yrB[0]=pB0; yrB[1]=pB1; yrB[2]=pB2; yrB[3]=pB3;
    }
}

__global__ __launch_bounds__(NT, 2)
void encoder_kernel(const float* __restrict__ s_img, const float* __restrict__ q_img,
                    const float* __restrict__ wf)
{
    extern __shared__ float sm[];
    const int n = blockIdx.x;
    const int t = threadIdx.x;

    float* s1  = sm + OFF_S1;
    float* s2  = sm + OFF_S2;
    float* w2s = sm + OFF_W2;
    float* w1s = sm + OFF_W1;
    float* f3  = sm + OFF_F3;
    float* red = sm + OFF_RED;

    const float* inp = (n < NSUP) ? (s_img + (size_t)n*(CIN*LIN))
                                  : (q_img + (size_t)(n - NSUP)*(CIN*LIN));

    // ---- phase A: zero pads; stage w1 (group 0) and w2 (group 1) ----
    if (t < 32) { s1[t*260]=0.f; s1[t*260+257]=0.f; s1[t*260+258]=0.f; s1[t*260+259]=0.f; }
    if (t < 64) { s2[t*132]=0.f; s2[t*132+129]=0.f; s2[t*132+130]=0.f; s2[t*132+131]=0.f; }
    {
        if (t < 192) cp_async16(smem_u32(w1s) + 16*t, (const char*)g_w1p + 16*t);
        cp_async_commit();
        uint32_t w2a = smem_u32(w2s);
        for (int e = t; e < 1536; e += NT)
            cp_async16(w2a + 16*e, (const char*)g_w2p + 16*e);
        cp_async_commit();
        cp_async_wait<1>();                  // w1 landed; w2 still in flight
    }
    __syncthreads();

    // ---- stage 1: conv(8->32,L512) from GMEM, w1 in smem; Q=64, 2 iters ----
    #pragma unroll
    for (int it = 0; it < 2; ++it) {
        int T = it*NT + t;
        int q = T & 63, ot = T >> 6;     // o0 0..28
        int o0 = 4*ot, l0 = 8*q;
        ull acc[2][8];
        #pragma unroll
        for (int p = 0; p < 2; ++p)
            #pragma unroll
            for (int j = 0; j < 8; ++j) acc[p][j] = 0ull;

        const ull* wp = reinterpret_cast<const ull*>(w1s) + (o0>>1)*24;
        #pragma unroll
        for (int i = 0; i < 8; ++i) {
            const float* xr = inp + i*LIN + l0;
            float4 xa = *reinterpret_cast<const float4*>(xr);
            float4 xb = *reinterpret_cast<const float4*>(xr + 4);
            ull xs[10];
            xs[0] = splat2((q > 0)  ? __ldg(xr - 1) : 0.f);
            xs[9] = splat2((q < 63) ? __ldg(xr + 8) : 0.f);
            xs[1]=splat2(xa.x); xs[2]=splat2(xa.y); xs[3]=splat2(xa.z); xs[4]=splat2(xa.w);
            xs[5]=splat2(xb.x); xs[6]=splat2(xb.y); xs[7]=splat2(xb.z); xs[8]=splat2(xb.w);
            ull wa0 = wp[3*i], wa1 = wp[3*i+1], wa2 = wp[3*i+2];
            ull wb0 = wp[24+3*i], wb1 = wp[24+3*i+1], wb2 = wp[24+3*i+2];
            #pragma unroll
            for (int j = 0; j < 8; ++j) {
                acc[0][j] = ffma2(wa2, xs[j+2], ffma2(wa1, xs[j+1], ffma2(wa0, xs[j], acc[0][j])));
                acc[1][j] = ffma2(wb2, xs[j+2], ffma2(wb1, xs[j+1], ffma2(wb0, xs[j], acc[1][j])));
            }
        }
        conv_epi_store(acc, o0, q,
                       reinterpret_cast<const ull*>(g_sc1),
                       reinterpret_cast<const ull*>(g_bi1), s1, 260);
    }
    cp_async_wait<0>();    // w2 landed
    __syncthreads();

    // ---- stage 2: conv(32->64,L256) -> s2; Q=32, 2 iters ----
    #pragma unroll
    for (int it = 0; it < 2; ++it) {
        int T = it*NT + t;
        int q = T & 31, ot = T >> 5;     // o0 0..60
        int o0 = 4*ot;
        ull acc[2][8];
        #pragma unroll
        for (int p = 0; p < 2; ++p)
            #pragma unroll
            for (int j = 0; j < 8; ++j) acc[p][j] = 0ull;
        conv_accum<32, 260>(s1 + 8*q,
                            reinterpret_cast<const ull*>(w2s) + (o0>>1)*96, acc);
        conv_epi_store(acc, o0, q,
                       reinterpret_cast<const ull*>(g_sc2),
                       reinterpret_cast<const ull*>(g_bi2), s2, 132);
    }
    __syncthreads();

    // ---- stage 3: conv(64->128,L128)+pool+sum(mean folded) -> f3 ----
    // NO staging: w3 read via uniform __ldg (L1/L2-resident, warp-uniform).
    {
        const int q = t & 15, ot = t >> 4;
        const ull* scp = reinterpret_cast<const ull*>(g_sc3);
        const ull* bip = reinterpret_cast<const ull*>(g_bi3);
        const ull* w3u = reinterpret_cast<const ull*>(g_w3p);

        #pragma unroll
        for (int g = 0; g < 2; ++g) {
            const int o0 = 64*g + 4*ot;
            ull acc[2][8];
            #pragma unroll
            for (int p = 0; p < 2; ++p)
                #pragma unroll
                for (int j = 0; j < 8; ++j) acc[p][j] = 0ull;
            conv_accum_g<64, 132>(s2 + 8*q, w3u + (o0>>1)*192, acc);

            #pragma unroll
            for (int p = 0; p < 2; ++p) {
                int pr = (o0 >> 1) + p;
                ull s2v = __ldg(scp + pr), b2v = __ldg(bip + pr);
                float a[8], b[8];
                #pragma unroll
                for (int j = 0; j < 8; ++j) {
                    ull y = ffma2(acc[p][j], s2v, b2v);
                    unpack2(y, a[j], b[j]);
                }
                float vA = fmaxf(fmaxf(a[0],0.f), fmaxf(a[1],0.f))
                         + fmaxf(fmaxf(a[2],0.f), fmaxf(a[3],0.f))
                         + fmaxf(fmaxf(a[4],0.f), fmaxf(a[5],0.f))
                         + fmaxf(fmaxf(a[6],0.f), fmaxf(a[7],0.f));
                float vB = fmaxf(fmaxf(b[0],0.f), fmaxf(b[1],0.f))
                         + fmaxf(fmaxf(b[2],0.f), fmaxf(b[3],0.f))
                         + fmaxf(fmaxf(b[4],0.f), fmaxf(b[5],0.f))
                         + fmaxf(fmaxf(b[6],0.f), fmaxf(b[7],0.f));
                #pragma unroll
                for (int sh = 8; sh; sh >>= 1) {      // reduce within 16-lane half
                    vA += __shfl_xor_sync(0xffffffffu, vA, sh);
                    vB += __shfl_xor_sync(0xffffffffu, vB, sh);
                }
                if (q == 0) { f3[2*pr] = vA; f3[2*pr+1] = vB; }
            }
        }
    }
    __syncthreads();

    // ---- stage 4: FC, BN, ReLU, L2 normalize (mean already folded) ----
    float hval = 0.f;
    if (t < 128) {
        const float4* wrow = reinterpret_cast<const float4*>(wf + (size_t)t*FDIM);
        float z = 0.f;
        #pragma unroll
        for (int e = 0; e < 32; ++e) {
            float4 wv = __ldg(wrow + e);
            float4 fv = *reinterpret_cast<const float4*>(f3 + 4*e);
            z = fmaf(wv.x, fv.x, z); z = fmaf(wv.y, fv.y, z);
            z = fmaf(wv.z, fv.z, z); z = fmaf(wv.w, fv.w, z);
        }
        hval = fmaxf(fmaf(z, __ldg(g_scf + t), __ldg(g_bif + t)), 0.f);
        float r2 = hval*hval;
        #pragma unroll
        for (int sh = 16; sh; sh >>= 1) r2 += __shfl_xor_sync(0xffffffffu, r2, sh);
        if ((t & 31) == 0) red[t >> 5] = r2;
    }
    __syncthreads();
    if (t == 0) {
        float s = red[0] + red[1] + red[2] + red[3];
        red[8] = 1.0f / fmaxf(sqrtf(s), 1e-12f);
    }
    __syncthreads();
    if (t < 128) g_feat[(size_t)n*FDIM + t] = hval * red[8];
}

// ---- prototypes ----
__global__ __launch_bounds__(256)
void proto_kernel(const int* __restrict__ s_lab)
{
    __shared__ float proto[NWAY*FDIM];
    __shared__ float cnt[NWAY];
    const int b = blockIdx.x, t = threadIdx.x;
    for (int e = t; e < NWAY*FDIM; e += 256) proto[e] = 0.f;
    if (t < NWAY) cnt[t] = 0.f;
    __syncthreads();

    const int g = t >> 7, f = t & 127;
    for (int s = g; s < NS; s += 2) {
        int lab = __ldg(s_lab + b*NS + s);
        atomicAdd(&proto[lab*FDIM + f], g_feat[(size_t)(b*NS + s)*FDIM + f]);
    }
    for (int s = t; s < NS; s += 256) atomicAdd(&cnt[__ldg(s_lab + b*NS + s)], 1.f);
    __syncthreads();

    for (int e = t; e < NWAY*FDIM; e += 256)
        g_proto[(size_t)b*NWAY*FDIM + e] = proto[e] / cnt[e >> 7];
}

// ---- distances: grid (B_EP, 4) ----
__global__ __launch_bounds__(256)
void dist_kernel(float* __restrict__ out)
{
    __shared__ float proto[NWAY*132];
    const int b = blockIdx.x, t = threadIdx.x;
    for (int e = t; e < NWAY*FDIM; e += 256)
        proto[(e >> 7)*132 + (e & 127)] = g_proto[(size_t)b*NWAY*FDIM + e];
    __syncthreads();

    const int base = 500*blockIdx.y, lim = base + 500;
    for (int pr = base + t; pr < lim; pr += 256) {
        int q = pr / NWAY, w = pr % NWAY;
        const float4* qf = reinterpret_cast<const float4*>(
            g_feat + (size_t)(NSUP + b*NQ + q)*FDIM);
        const float4* pw = reinterpret_cast<const float4*>(proto + w*132);
        float d = 0.f;
        #pragma unroll
        for (int e = 0; e < 32; ++e) {
            float4 a = __ldg(qf + e);
            float4 p = pw[e];
            float dx = a.x-p.x, dy = a.y-p.y, dz = a.z-p.z, dw = a.w-p.w;
            d = fmaf(dx,dx, fmaf(dy,dy, fmaf(dz,dz, fmaf(dw,dw, d))));
        }
        out[(size_t)b*NQ*NWAY + pr] = -sqrtf(fmaxf(d, 0.f));
    }
}

extern "C" void kernel_launch(void* const* d_in, const int* in_sizes, int n_in,
                              void* d_out, int out_size)
{
    const float* s_img = (const float*)d_in[0];
    const float* q_img = (const float*)d_in[1];
    const int*   s_lab = (const int*)  d_in[2];
    const float* w1  = (const float*)d_in[3];
    const float* b1  = (const float*)d_in[4];
    const float* g1  = (const float*)d_in[5];
    const float* be1 = (const float*)d_in[6];
    const float* m1  = (const float*)d_in[7];
    const float* v1  = (const float*)d_in[8];
    const float* w2  = (const float*)d_in[9];
    const float* b2  = (const float*)d_in[10];
    const float* g2  = (const float*)d_in[11];
    const float* be2 = (const float*)d_in[12];
    const float* m2  = (const float*)d_in[13];
    const float* v2  = (const float*)d_in[14];
    const float* w3  = (const float*)d_in[15];
    const float* b3  = (const float*)d_in[16];
    const float* g3  = (const float*)d_in[17];
    const float* be3 = (const float*)d_in[18];
    const float* m3  = (const float*)d_in[19];
    const float* v3  = (const float*)d_in[20];
    const float* wf  = (const float*)d_in[21];
    const float* bf  = (const float*)d_in[22];
    const float* gf  = (const float*)d_in[23];
    const float* bef = (const float*)d_in[24];
    const float* mf  = (const float*)d_in[25];
    const float* vf  = (const float*)d_in[26];
    float* out = (float*)d_out;

    cudaFuncSetAttribute(encoder_kernel,
                         cudaFuncAttributeMaxDynamicSharedMemorySize, SMEM_BYTES);

    prep_kernel<<<24, 512>>>(w1, b1, g1, be1, m1, v1,
                             w2, b2, g2, be2, m2, v2,
                             w3, b3, g3, be3, m3, v3,
                             bf, gf, bef, mf, vf);
    encoder_kernel<<<NTOT, NT, SMEM_BYTES>>>(s_img, q_img, wf);
    proto_kernel<<<B_EP, 256>>>(s_lab);
    dist_kernel<<<dim3(B_EP, 4), 256>>>(out);
}

// round 17
// speedup vs baseline: 1.0839x; 1.0839x over previous
#include <cuda_runtime.h>
#include <cstdint>
#include <math.h>

#define EPS_BN 1e-5f

// ---- problem constants ----
#define B_EP   32
#define NS     200
#define NQ     100
#define NWAY   20
#define CIN    8
#define LIN    512
#define FDIM   128
#define NSUP   (B_EP*NS)     // 6400
#define NQRY   (B_EP*NQ)     // 3200
#define NTOT   (NSUP+NQRY)   // 9600
#define NT     256           // encoder threads per CTA (2 CTAs/SM)

typedef unsigned long long ull;

// ---- device scratch ----
__device__ float g_feat[NTOT*FDIM];
// pre-interleaved weights + folded BN (written once by prep_kernel)
__device__ float g_w1p[768];        // [pair][ic*3][2]
__device__ float g_w2p[6144];       // [pair][ic*3][2]
__device__ float g_w3p[24576];      // [oc-half][pairl][ic*3][2]  (pair stride 384 floats)
__device__ float g_sc1[32],  g_bi1[32];
__device__ float g_sc2[64],  g_bi2[64];
__device__ float g_sc3[128], g_bi3[128];   // include 1/64 mean fold
__device__ float g_scf[128], g_bif[128];

// ---- shared memory layout (float offsets), total 27808 floats = 111.2KB ----
// region A [0,12288): s1 (32x260=8320) during stages 1-2, then w3 OC-halves
#define OFF_S1   0
#define OFF_W3H  0
#define OFF_S2   12288        // 64 x 132 = 8448
#define OFF_W2   20736        // 6144
#define OFF_W1   26880        // 768
#define OFF_F3   27648        // 128
#define OFF_RED  27776        // 32
#define SMEM_FLOATS 27808
#define SMEM_BYTES  (SMEM_FLOATS*4)

// ---- packed f32x2 helpers ----
__device__ __forceinline__ ull ffma2(ull a, ull b, ull c) {
    ull d;
    asm("fma.rn.f32x2 %0, %1, %2, %3;" : "=l"(d) : "l"(a), "l"(b), "l"(c));
    return d;
}
__device__ __forceinline__ ull splat2(float x) {
    ull d;
    asm("mov.b64 %0, {%1, %1};" : "=l"(d) : "f"(x));
    return d;
}
__device__ __forceinline__ void unpack2(ull v, float& lo, float& hi) {
    asm("mov.b64 {%0, %1}, %2;" : "=f"(lo), "=f"(hi) : "l"(v));
}
__device__ __forceinline__ uint32_t smem_u32(const void* p) {
    uint32_t a;
    asm("{ .reg .u64 t; cvta.to.shared.u64 t, %1; cvt.u32.u64 %0, t; }"
        : "=r"(a) : "l"(p));
    return a;
}
__device__ __forceinline__ void cp_async16(uint32_t saddr, const void* g) {
    asm volatile("cp.async.cg.shared.global [%0], [%1], 16;" :: "r"(saddr), "l"(g));
}
__device__ __forceinline__ void cp_async_wait_all() {
    asm volatile("cp.async.commit_group;\ncp.async.wait_group 0;" ::: "memory");
}

// ---- one-time prep (grid=24): pair-interleave conv weights, fold BN ----
__global__ __launch_bounds__(512)
void prep_kernel(const float* __restrict__ w1, const float* __restrict__ b1,
                 const float* __restrict__ g1, const float* __restrict__ be1,
                 const float* __restrict__ m1, const float* __restrict__ v1,
                 const float* __restrict__ w2, const float* __restrict__ b2,
                 const float* __restrict__ g2, const float* __restrict__ be2,
                 const float* __restrict__ m2, const float* __restrict__ v2,
                 const float* __restrict__ w3, const float* __restrict__ b3,
                 const float* __restrict__ g3, const float* __restrict__ be3,
                 const float* __restrict__ m3, const float* __restrict__ v3,
                 const float* __restrict__ bf, const float* __restrict__ gf,
                 const float* __restrict__ bef, const float* __restrict__ mf,
                 const float* __restrict__ vf)
{
    const int t = blockIdx.x*512 + threadIdx.x;
    const int STR = gridDim.x*512;
    for (int f = t; f < 768; f += STR) {
        int o = f/24, r = f - o*24;
        g_w1p[(o>>1)*48 + 2*r + (o&1)] = w1[f];
    }
    for (int f = t; f < 6144; f += STR) {
        int o = f/96, r = f - o*96;
        g_w2p[(o>>1)*192 + 2*r + (o&1)] = w2[f];
    }
    // OC-half layout: w3[o][i][k] -> g_w3p[(o>>6)*12288 + ((o&63)>>1)*384 + 2*r + (o&1)]
    for (int f = t; f < 24576; f += STR) {
        int o = f/192, r = f - o*192;
        int half = o >> 6, ol = o & 63;
        g_w3p[half*12288 + (ol>>1)*384 + 2*r + (ol&1)] = w3[f];
    }
    if (t < 32) {
        float s = g1[t]*rsqrtf(v1[t]+EPS_BN);
        g_sc1[t]=s; g_bi1[t]=(b1[t]-m1[t])*s+be1[t];
    } else if (t < 96) {
        int i=t-32; float s = g2[i]*rsqrtf(v2[i]+EPS_BN);
        g_sc2[i]=s; g_bi2[i]=(b2[i]-m2[i])*s+be2[i];
    } else if (t < 224) {
        // fold 1/64 AdaptiveAvgPool mean into BN scale/bias
        int i=t-96; float s = g3[i]*rsqrtf(v3[i]+EPS_BN);
        g_sc3[i]=s*(1.0f/64.0f);
        g_bi3[i]=((b3[i]-m3[i])*s+be3[i])*(1.0f/64.0f);
    } else if (t < 352) {
        int i=t-224; float s = gf[i]*rsqrtf(vf[i]+EPS_BN);
        g_scf[i]=s; g_bif[i]=(bf[i]-mf[i])*s+bef[i];
    }
}

// Accumulate conv1d(k=3) into packed acc[2 pairs][8 positions], x and W in smem.
template<int IC, int XRS>
__device__ __forceinline__ void conv_accum(const float* __restrict__ xcol,
                                           const ull* __restrict__ wbase,
                                           ull (&acc)[2][8])
{
    constexpr int IC3 = IC*3;
    #pragma unroll 4
    for (int i = 0; i < IC; ++i) {
        const float* xr = xcol + i*XRS;
        float4 xa = *reinterpret_cast<const float4*>(xr);
        float4 xb = *reinterpret_cast<const float4*>(xr + 4);
        float2 xc = *reinterpret_cast<const float2*>(xr + 8);
        ull xs[10];
        xs[0]=splat2(xa.x); xs[1]=splat2(xa.y); xs[2]=splat2(xa.z); xs[3]=splat2(xa.w);
        xs[4]=splat2(xb.x); xs[5]=splat2(xb.y); xs[6]=splat2(xb.z); xs[7]=splat2(xb.w);
        xs[8]=splat2(xc.x); xs[9]=splat2(xc.y);
        const ull* w0r = wbase + 3*i;
        const ull* w1r = wbase + IC3 + 3*i;
        ull wa0 = w0r[0], wa1 = w0r[1], wa2 = w0r[2];
        ull wb0 = w1r[0], wb1 = w1r[1], wb2 = w1r[2];
        #pragma unroll
        for (int j = 0; j < 8; ++j) {
            acc[0][j] = ffma2(wa2, xs[j+2], ffma2(wa1, xs[j+1], ffma2(wa0, xs[j], acc[0][j])));
            acc[1][j] = ffma2(wb2, xs[j+2], ffma2(wb1, xs[j+1], ffma2(wb0, xs[j], acc[1][j])));
        }
    }
}

// Epilogue: packed BN + ReLU + maxpool2, store 4 pooled per channel.
__device__ __forceinline__ void conv_epi_store(ull (&acc)[2][8], int o0, int q,
                                               const ull* __restrict__ scp,
                                               const ull* __restrict__ bip,
                                               float* __restrict__ Y, int YRS)
{
    #pragma unroll
    for (int p = 0; p < 2; ++p) {
        int pr = (o0 >> 1) + p;
        ull s2 = __ldg(scp + pr), b2 = __ldg(bip + pr);
        float a[8], b[8];
        #pragma unroll
        for (int j = 0; j < 8; ++j) {
            ull y = ffma2(acc[p][j], s2, b2);
            unpack2(y, a[j], b[j]);
        }
        float pA0 = fmaxf(fmaxf(a[0],0.f), fmaxf(a[1],0.f));
        float pA1 = fmaxf(fmaxf(a[2],0.f), fmaxf(a[3],0.f));
        float pA2 = fmaxf(fmaxf(a[4],0.f), fmaxf(a[5],0.f));
        float pA3 = fmaxf(fmaxf(a[6],0.f), fmaxf(a[7],0.f));
        float pB0 = fmaxf(fmaxf(b[0],0.f), fmaxf(b[1],0.f));
        float pB1 = fmaxf(fmaxf(b[2],0.f), fmaxf(b[3],0.f));
        float pB2 = fmaxf(fmaxf(b[4],0.f), fmaxf(b[5],0.f));
        float pB3 = fmaxf(fmaxf(b[6],0.f), fmaxf(b[7],0.f));
        float* yrA = Y + (2*pr)*YRS + 1 + 4*q;
        float* yrB = Y + (2*pr+1)*YRS + 1 + 4*q;
        yrA[0]=pA0; yrA[1]=pA1; yrA[2]=pA2; yrA[3]=pA3;
        yrB[0]=pB0; yrB[1]=pB1; yrB[2]=pB2; yrB[3]=pB3;
    }
}

__global__ __launch_bounds__(NT, 2)
void encoder_kernel(const float* __restrict__ s_img, const float* __restrict__ q_img,
                    const float* __restrict__ wf)
{
    extern __shared__ float sm[];
    const int n = blockIdx.x;
    const int t = threadIdx.x;

    float* s1  = sm + OFF_S1;
    float* w3h = sm + OFF_W3H;
    float* s2  = sm + OFF_S2;
    float* w2s = sm + OFF_W2;
    float* w1s = sm + OFF_W1;
    float* f3  = sm + OFF_F3;
    float* red = sm + OFF_RED;

    const float* inp = (n < NSUP) ? (s_img + (size_t)n*(CIN*LIN))
                                  : (q_img + (size_t)(n - NSUP)*(CIN*LIN));

    // ---- phase A: zero pads + stage w1/w2 (cp.async, contiguous) ----
    if (t < 32) { s1[t*260]=0.f; s1[t*260+257]=0.f; s1[t*260+258]=0.f; s1[t*260+259]=0.f; }
    if (t < 64) { s2[t*132]=0.f; s2[t*132+129]=0.f; s2[t*132+130]=0.f; s2[t*132+131]=0.f; }
    {
        if (t < 192) cp_async16(smem_u32(w1s) + 16*t, (const char*)g_w1p + 16*t);
        uint32_t w2a = smem_u32(w2s);
        for (int e = t; e < 1536; e += NT)
            cp_async16(w2a + 16*e, (const char*)g_w2p + 16*e);
        cp_async_wait_all();
    }
    __syncthreads();

    // ---- stage 1: conv(8->32,L512) from GMEM, w1 in smem; Q=64, 2 iters ----
    #pragma unroll
    for (int it = 0; it < 2; ++it) {
        int T = it*NT + t;
        int q = T & 63, ot = T >> 6;     // o0 0..28
        int o0 = 4*ot, l0 = 8*q;
        ull acc[2][8];
        #pragma unroll
        for (int p = 0; p < 2; ++p)
            #pragma unroll
            for (int j = 0; j < 8; ++j) acc[p][j] = 0ull;

        const ull* wp = reinterpret_cast<const ull*>(w1s) + (o0>>1)*24;
        #pragma unroll
        for (int i = 0; i < 8; ++i) {
            const float* xr = inp + i*LIN + l0;
            float4 xa = *reinterpret_cast<const float4*>(xr);
            float4 xb = *reinterpret_cast<const float4*>(xr + 4);
            ull xs[10];
            xs[0] = splat2((q > 0)  ? __ldg(xr - 1) : 0.f);
            xs[9] = splat2((q < 63) ? __ldg(xr + 8) : 0.f);
            xs[1]=splat2(xa.x); xs[2]=splat2(xa.y); xs[3]=splat2(xa.z); xs[4]=splat2(xa.w);
            xs[5]=splat2(xb.x); xs[6]=splat2(xb.y); xs[7]=splat2(xb.z); xs[8]=splat2(xb.w);
            ull wa0 = wp[3*i], wa1 = wp[3*i+1], wa2 = wp[3*i+2];
            ull wb0 = wp[24+3*i], wb1 = wp[24+3*i+1], wb2 = wp[24+3*i+2];
            #pragma unroll
            for (int j = 0; j < 8; ++j) {
                acc[0][j] = ffma2(wa2, xs[j+2], ffma2(wa1, xs[j+1], ffma2(wa0, xs[j], acc[0][j])));
                acc[1][j] = ffma2(wb2, xs[j+2], ffma2(wb1, xs[j+1], ffma2(wb0, xs[j], acc[1][j])));
            }
        }
        conv_epi_store(acc, o0, q,
                       reinterpret_cast<const ull*>(g_sc1),
                       reinterpret_cast<const ull*>(g_bi1), s1, 260);
    }
    __syncthreads();

    // ---- stage 2: conv(32->64,L256) -> s2; Q=32, 2 iters ----
    #pragma unroll
    for (int it = 0; it < 2; ++it) {
        int T = it*NT + t;
        int q = T & 31, ot = T >> 5;     // o0 0..60
        int o0 = 4*ot;
        ull acc[2][8];
        #pragma unroll
        for (int p = 0; p < 2; ++p)
            #pragma unroll
            for (int j = 0; j < 8; ++j) acc[p][j] = 0ull;
        conv_accum<32, 260>(s1 + 8*q,
                            reinterpret_cast<const ull*>(w2s) + (o0>>1)*96, acc);
        conv_epi_store(acc, o0, q,
                       reinterpret_cast<const ull*>(g_sc2),
                       reinterpret_cast<const ull*>(g_bi2), s2, 132);
    }
    __syncthreads();

    // ---- stage 3: conv(64->128,L128)+pool+sum(mean folded) -> f3; two OC halves ----
    {
        const int q = t & 15, ot = t >> 4;   // local o0 0..60
        const int o0l = 4*ot;
        const ull* scp = reinterpret_cast<const ull*>(g_sc3);
        const ull* bip = reinterpret_cast<const ull*>(g_bi3);
        const uint32_t w3a = smem_u32(w3h);

        #pragma unroll
        for (int h = 0; h < 2; ++h) {
            const char* src = (const char*)(g_w3p + h*12288);
            for (int e = t; e < 3072; e += NT)
                cp_async16(w3a + 16*e, src + 16*e);
            cp_async_wait_all();
            __syncthreads();

            ull acc[2][8];
            #pragma unroll
            for (int p = 0; p < 2; ++p)
                #pragma unroll
                for (int j = 0; j < 8; ++j) acc[p][j] = 0ull;
            conv_accum<64, 132>(s2 + 8*q,
                                reinterpret_cast<const ull*>(w3h) + (o0l>>1)*192, acc);

            #pragma unroll
            for (int p = 0; p < 2; ++p) {
                int pr = 32*h + (o0l >> 1) + p;
                ull s2v = __ldg(scp + pr), b2v = __ldg(bip + pr);
                float a[8], b[8];
                #pragma unroll
                for (int j = 0; j < 8; ++j) {
                    ull y = ffma2(acc[p][j], s2v, b2v);
                    unpack2(y, a[j], b[j]);
                }
                float vA = fmaxf(fmaxf(a[0],0.f), fmaxf(a[1],0.f))
                         + fmaxf(fmaxf(a[2],0.f), fmaxf(a[3],0.f))
                         + fmaxf(fmaxf(a[4],0.f), fmaxf(a[5],0.f))
                         + fmaxf(fmaxf(a[6],0.f), fmaxf(a[7],0.f));
                float vB = fmaxf(fmaxf(b[0],0.f), fmaxf(b[1],0.f))
                         + fmaxf(fmaxf(b[2],0.f), fmaxf(b[3],0.f))
                         + fmaxf(fmaxf(b[4],0.f), fmaxf(b[5],0.f))
                         + fmaxf(fmaxf(b[6],0.f), fmaxf(b[7],0.f));
                #pragma unroll
                for (int sh = 8; sh; sh >>= 1) {      // reduce within 16-lane half
                    vA += __shfl_xor_sync(0xffffffffu, vA, sh);
                    vB += __shfl_xor_sync(0xffffffffu, vB, sh);
                }
                if (q == 0) { f3[2*pr] = vA; f3[2*pr+1] = vB; }
            }
            __syncthreads();   // half h consumed before half h+1 overwrites w3h
        }
    }

    // ---- stage 4: FC, BN, ReLU, L2 normalize (mean already folded) ----
    float hval = 0.f;
    if (t < 128) {
        const float4* wrow = reinterpret_cast<const float4*>(wf + (size_t)t*FDIM);
        float z = 0.f;
        #pragma unroll
        for (int e = 0; e < 32; ++e) {
            float4 wv = __ldg(wrow + e);
            float4 fv = *reinterpret_cast<const float4*>(f3 + 4*e);
            z = fmaf(wv.x, fv.x, z); z = fmaf(wv.y, fv.y, z);
            z = fmaf(wv.z, fv.z, z); z = fmaf(wv.w, fv.w, z);
        }
        hval = fmaxf(fmaf(z, __ldg(g_scf + t), __ldg(g_bif + t)), 0.f);
        float r2 = hval*hval;
        #pragma unroll
        for (int sh = 16; sh; sh >>= 1) r2 += __shfl_xor_sync(0xffffffffu, r2, sh);
        if ((t & 31) == 0) red[t >> 5] = r2;
    }
    __syncthreads();
    if (t == 0) {
        float s = red[0] + red[1] + red[2] + red[3];
        red[8] = 1.0f / fmaxf(sqrtf(s), 1e-12f);
    }
    __syncthreads();
    if (t < 128) g_feat[(size_t)n*FDIM + t] = hval * red[8];
}

// ---- fused prototypes + distances: grid (B_EP, 4) ----
// Each block: builds episode-b prototypes in smem (redundant across y — free),
// caches its 25-query slice in smem, computes 500 distances all from smem.
__global__ __launch_bounds__(256)
void proto_dist_kernel(const int* __restrict__ s_lab, float* __restrict__ out)
{
    __shared__ float proto[NWAY*132];   // padded stride
    __shared__ float cnt[NWAY];
    __shared__ float qsm[25*132];       // this block's 25 queries, padded stride
    const int b = blockIdx.x, t = threadIdx.x;
    const int qbase = 25*blockIdx.y;

    for (int e = t; e < NWAY*132; e += 256) proto[e] = 0.f;
    if (t < NWAY) cnt[t] = 0.f;
    // load 25 queries (each row 128 floats, coalesced)
    for (int e = t; e < 25*FDIM; e += 256) {
        int q = e >> 7, f = e & 127;
        qsm[q*132 + f] = g_feat[(size_t)(NSUP + b*NQ + qbase + q)*FDIM + f];
    }
    __syncthreads();

    // accumulate prototypes (smem atomics, spread addresses)
    const int g = t >> 7, f = t & 127;
    for (int s = g; s < NS; s += 2) {
        int lab = __ldg(s_lab + b*NS + s);
        atomicAdd(&proto[lab*132 + f], g_feat[(size_t)(b*NS + s)*FDIM + f]);
    }
    for (int s = t; s < NS; s += 256) atomicAdd(&cnt[__ldg(s_lab + b*NS + s)], 1.f);
    __syncthreads();

    if (t < NWAY) cnt[t] = 1.0f / cnt[t];
    __syncthreads();
    for (int e = t; e < NWAY*FDIM; e += 256) {
        int w = e >> 7, ff = e & 127;
        proto[w*132 + ff] *= cnt[w];
    }
    __syncthreads();

    // distances: 500 pairs, all operands in smem
    for (int pr = t; pr < 25*NWAY; pr += 256) {
        int q = pr / NWAY, w = pr % NWAY;
        const float4* qf = reinterpret_cast<const float4*>(qsm + q*132);
        const float4* pw = reinterpret_cast<const float4*>(proto + w*132);
        float d = 0.f;
        #pragma unroll
        for (int e = 0; e < 32; ++e) {
            float4 a = qf[e];
            float4 p = pw[e];
            float dx = a.x-p.x, dy = a.y-p.y, dz = a.z-p.z, dw = a.w-p.w;
            d = fmaf(dx,dx, fmaf(dy,dy, fmaf(dz,dz, fmaf(dw,dw, d))));
        }
        out[(size_t)b*NQ*NWAY + (qbase + q)*NWAY + w] = -sqrtf(fmaxf(d, 0.f));
    }
}

extern "C" void kernel_launch(void* const* d_in, const int* in_sizes, int n_in,
                              void* d_out, int out_size)
{
    const float* s_img = (const float*)d_in[0];
    const float* q_img = (const float*)d_in[1];
    const int*   s_lab = (const int*)  d_in[2];
    const float* w1  = (const float*)d_in[3];
    const float* b1  = (const float*)d_in[4];
    const float* g1  = (const float*)d_in[5];
    const float* be1 = (const float*)d_in[6];
    const float* m1  = (const float*)d_in[7];
    const float* v1  = (const float*)d_in[8];
    const float* w2  = (const float*)d_in[9];
    const float* b2  = (const float*)d_in[10];
    const float* g2  = (const float*)d_in[11];
    const float* be2 = (const float*)d_in[12];
    const float* m2  = (const float*)d_in[13];
    const float* v2  = (const float*)d_in[14];
    const float* w3  = (const float*)d_in[15];
    const float* b3  = (const float*)d_in[16];
    const float* g3  = (const float*)d_in[17];
    const float* be3 = (const float*)d_in[18];
    const float* m3  = (const float*)d_in[19];
    const float* v3  = (const float*)d_in[20];
    const float* wf  = (const float*)d_in[21];
    const float* bf  = (const float*)d_in[22];
    const float* gf  = (const float*)d_in[23];
    const float* bef = (const float*)d_in[24];
    const float* mf  = (const float*)d_in[25];
    const float* vf  = (const float*)d_in[26];
    float* out = (float*)d_out;

    cudaFuncSetAttribute(encoder_kernel,
                         cudaFuncAttributeMaxDynamicSharedMemorySize, SMEM_BYTES);

    prep_kernel<<<24, 512>>>(w1, b1, g1, be1, m1, v1,
                             w2, b2, g2, be2, m2, v2,
                             w3, b3, g3, be3, m3, v3,
                             bf, gf, bef, mf, vf);
    encoder_kernel<<<NTOT, NT, SMEM_BYTES>>>(s_img, q_img, wf);
    proto_dist_kernel<<<dim3(B_EP, 4), 256>>>(s_lab, out);
}